// round 11
// baseline (speedup 1.0000x reference)
#include <cuda_runtime.h>
#include <cstdint>

// YOLO post-process: (16, 25200, 85) fp32 -> (16, 25200, 6) fp32
//
// R10: 3 persistent blocks/SM (444 blocks, 12 warps/SM), depth-2 cp.async.bulk
//      pipeline of 104-row (35360 B) tiles. More independent block loops per SM
//      de-correlate the per-loop serial windows (wake+compute+store) so the
//      copy path never idles. Contiguous quad-aligned chunks, staged float4
//      output epilogue. Zero global coordination.

#define N_ROWS        403200          // 16 * 25200
#define N_CH          85
#define N_OUT         6
#define CONF_TH       0.25f
#define TILE_ROWS     104
#define BLOCK_THREADS 128
#define TILE_FLOATS   (TILE_ROWS * N_CH)     // 8840
#define TILE_BYTES    (TILE_FLOATS * 4)      // 35360
#define OUT_FLOATS    (TILE_ROWS * N_OUT)    // 624
#define GRID_BLOCKS   444                    // 3 per SM * 148

// Chunking in quad-rows (4 rows = 1360 B -> every bulk-copy source 16B-aligned):
//   total quads = 100800 = 444*227 + 12 -> first 12 blocks get 228 quads.
#define QUADS_BASE    227
#define QUADS_EXTRA   12

// dynamic smem: [0,16) mbar[2], [32,+2*TILE_BYTES) in bufs, then 2 out bufs
#define SM_IN    32
#define SM_OUT   (SM_IN + 2 * TILE_BYTES)            // 70752
#define SM_TOTAL (SM_OUT + 2 * OUT_FLOATS * 4)       // 75744  (3x = 227232 <= 228KB)

__device__ __forceinline__ unsigned smem_u32(const void* p) {
    unsigned a;
    asm("{ .reg .u64 t; cvta.to.shared.u64 t, %1; cvt.u32.u64 %0, t; }"
        : "=r"(a) : "l"(p));
    return a;
}

__device__ __forceinline__ void mbar_init(unsigned addr, unsigned count) {
    asm volatile("mbarrier.init.shared.b64 [%0], %1;" :: "r"(addr), "r"(count) : "memory");
}

__device__ __forceinline__ void bulk_load(unsigned dst_smem, const void* gsrc,
                                          unsigned bytes, unsigned mbar) {
    asm volatile("mbarrier.arrive.expect_tx.shared.b64 _, [%0], %1;"
                 :: "r"(mbar), "r"(bytes) : "memory");
    asm volatile("cp.async.bulk.shared::cta.global.mbarrier::complete_tx::bytes "
                 "[%0], [%1], %2, [%3];"
                 :: "r"(dst_smem), "l"(gsrc), "r"(bytes), "r"(mbar) : "memory");
}

__device__ __forceinline__ void mbar_wait(unsigned addr, unsigned parity) {
    asm volatile(
        "{\n\t"
        ".reg .pred P;\n\t"
        "W%=:\n\t"
        "mbarrier.try_wait.parity.acquire.cta.shared::cta.b64 P, [%0], %1, 0x989680;\n\t"
        "@P bra D%=;\n\t"
        "bra W%=;\n\t"
        "D%=:\n\t"
        "}"
        :: "r"(addr), "r"(parity) : "memory");
}

__global__ __launch_bounds__(BLOCK_THREADS, 3)
void yolo_post_kernel(const float* __restrict__ in, float4* __restrict__ out4)
{
    extern __shared__ char sb[];
    const unsigned base = smem_u32(sb);
    float* const in_base  = reinterpret_cast<float*>(sb + SM_IN);
    float* const out_base = reinterpret_cast<float*>(sb + SM_OUT);

    const int tid = threadIdx.x;
    const int b   = blockIdx.x;

    // Contiguous chunk (quad-row granularity).
    const int q_start = QUADS_BASE * b + (b < QUADS_EXTRA ? b : QUADS_EXTRA);
    const int row0    = 4 * q_start;
    const int n_rows  = 4 * (QUADS_BASE + (b < QUADS_EXTRA ? 1 : 0));   // 912 or 908
    const int n_tiles = (n_rows + TILE_ROWS - 1) / TILE_ROWS;           // 9

    if (tid == 0) {
        mbar_init(base + 0, 1);
        mbar_init(base + 8, 1);
        // Prologue: issue DMA for tile 0 into slot 0.
        int tr0 = (n_rows < TILE_ROWS) ? n_rows : TILE_ROWS;
        bulk_load(base + SM_IN, in + (size_t)row0 * N_CH,
                  (unsigned)(tr0 * N_CH * 4), base + 0);
    }
    __syncthreads();

    for (int it = 0; it < n_tiles; ++it) {
        const int slot   = it & 1;
        const int slot_w = (it + 1) & 1;

        // Issue DMA for the next tile into the buffer freed last iteration.
        if (tid == 0 && it + 1 < n_tiles) {
            const int r_off = (it + 1) * TILE_ROWS;
            int tr = n_rows - r_off;
            if (tr > TILE_ROWS) tr = TILE_ROWS;
            bulk_load(base + SM_IN + slot_w * TILE_BYTES,
                      in + (size_t)(row0 + r_off) * N_CH,
                      (unsigned)(tr * N_CH * 4), base + slot_w * 8);
        }

        // Wait for current tile.
        mbar_wait(base + slot * 8, (unsigned)((it >> 1) & 1));

        const int r_off = it * TILE_ROWS;
        int tile_rows = n_rows - r_off;
        if (tile_rows > TILE_ROWS) tile_rows = TILE_ROWS;

        // ---- compute: thread-per-row (stride-85 LDS = conflict-free) ----
        float* ob = out_base + (it & 1) * OUT_FLOATS;
        if (tid < tile_rows) {
            const float* row = in_base + slot * TILE_FLOATS + tid * N_CH;

            const float x    = row[0];
            const float y    = row[1];
            const float w    = row[2];
            const float h    = row[3];
            const float conf = row[4];

            float b0 = row[5 +  0], b1 = row[5 + 20], b2 = row[5 + 40], b3 = row[5 + 60];
            int   i0 = 0,           i1 = 20,          i2 = 40,          i3 = 60;

            #pragma unroll
            for (int c = 1; c < 20; c++) {
                float v0 = row[5 +  0 + c];
                float v1 = row[5 + 20 + c];
                float v2 = row[5 + 40 + c];
                float v3 = row[5 + 60 + c];
                if (v0 > b0) { b0 = v0; i0 =  0 + c; }
                if (v1 > b1) { b1 = v1; i1 = 20 + c; }
                if (v2 > b2) { b2 = v2; i2 = 40 + c; }
                if (v3 > b3) { b3 = v3; i3 = 60 + c; }
            }
            // Ordered merge: ties keep the earlier quarter -> first-index semantics.
            if (b1 > b0) { b0 = b1; i0 = i1; }
            if (b2 > b0) { b0 = b2; i0 = i2; }
            if (b3 > b0) { b0 = b3; i0 = i3; }

            const float score = conf * b0;
            const bool  pass  = score > CONF_TH;
            const float hw = 0.5f * w;
            const float hh = 0.5f * h;

            float o0 = 0.f, o1 = 0.f, o2 = 0.f, o3 = 0.f, o4 = 0.f, o5 = 0.f;
            if (pass) {
                o0 = x - hw;
                o1 = y - hh;
                o2 = x + hw;
                o3 = y + hh;
                o4 = score;
                o5 = (float)i0;
            }

            float* so = ob + tid * N_OUT;
            so[0] = o0; so[1] = o1; so[2] = o2; so[3] = o3; so[4] = o4; so[5] = o5;
        }
        __syncthreads();   // LDS reads of in-buf done (slot reuse safe) + staging visible

        // ---- coalesced float4 store (tile_rows % 4 == 0 -> nvec integral) ----
        {
            const int nvec = (tile_rows * N_OUT) / 4;
            const float4* src = reinterpret_cast<const float4*>(ob);
            float4* dst = reinterpret_cast<float4*>(
                reinterpret_cast<float*>(out4) + (size_t)(row0 + r_off) * N_OUT);
            for (int i = tid; i < nvec; i += BLOCK_THREADS)
                dst[i] = src[i];
        }
    }
}

extern "C" void kernel_launch(void* const* d_in, const int* in_sizes, int n_in,
                              void* d_out, int out_size)
{
    const float* in  = (const float*)d_in[0];
    float4*      out = (float4*)d_out;
    cudaFuncSetAttribute(yolo_post_kernel,
                         cudaFuncAttributeMaxDynamicSharedMemorySize, SM_TOTAL);
    yolo_post_kernel<<<GRID_BLOCKS, BLOCK_THREADS, SM_TOTAL>>>(in, out);
}

// round 12
// speedup vs baseline: 1.0735x; 1.0735x over previous
#include <cuda_runtime.h>
#include <cstdint>

// YOLO post-process: (16, 25200, 85) fp32 -> (16, 25200, 6) fp32
//
// R11: R7 DMA structure (128-row/43520B tiles, depth-2 cp.async.bulk,
//      2 blocks/SM, static contiguous quad-aligned chunks) + split-row
//      compute: 256 threads, 2 threads per row (even lanes: classes 0-39,
//      odd lanes: classes 40-79 rotated by 8 for bank-conflict freedom),
//      exact index-aware tie-breaking, shfl_xor(1) pair combine.

#define N_ROWS        403200          // 16 * 25200
#define N_CH          85
#define N_OUT         6
#define CONF_TH       0.25f
#define TILE_ROWS     128
#define BLOCK_THREADS 256
#define TILE_FLOATS   (TILE_ROWS * N_CH)     // 10880
#define TILE_BYTES    (TILE_FLOATS * 4)      // 43520
#define OUT_FLOATS    (TILE_ROWS * N_OUT)    // 768
#define GRID_BLOCKS   296                    // 2 per SM * 148

// Chunking in quad-rows (4 rows = 1360 B -> bulk-copy sources 16B-aligned):
//   total quads = 100800 = 296*340 + 160 -> first 160 blocks get 341 quads.
#define QUADS_BASE    340
#define QUADS_EXTRA   160

// dynamic smem: [0,16) mbar[2], [32,+2T) in bufs, then 2 out bufs (3072 B)
#define SM_IN    32
#define SM_OUT   (SM_IN + 2 * TILE_BYTES)            // 87072
#define SM_TOTAL (SM_OUT + 2 * OUT_FLOATS * 4)       // 93216

__device__ __forceinline__ unsigned smem_u32(const void* p) {
    unsigned a;
    asm("{ .reg .u64 t; cvta.to.shared.u64 t, %1; cvt.u32.u64 %0, t; }"
        : "=r"(a) : "l"(p));
    return a;
}

__device__ __forceinline__ void mbar_init(unsigned addr, unsigned count) {
    asm volatile("mbarrier.init.shared.b64 [%0], %1;" :: "r"(addr), "r"(count) : "memory");
}

__device__ __forceinline__ void bulk_load(unsigned dst_smem, const void* gsrc,
                                          unsigned bytes, unsigned mbar) {
    asm volatile("mbarrier.arrive.expect_tx.shared.b64 _, [%0], %1;"
                 :: "r"(mbar), "r"(bytes) : "memory");
    asm volatile("cp.async.bulk.shared::cta.global.mbarrier::complete_tx::bytes "
                 "[%0], [%1], %2, [%3];"
                 :: "r"(dst_smem), "l"(gsrc), "r"(bytes), "r"(mbar) : "memory");
}

__device__ __forceinline__ void mbar_wait(unsigned addr, unsigned parity) {
    asm volatile(
        "{\n\t"
        ".reg .pred P;\n\t"
        "W%=:\n\t"
        "mbarrier.try_wait.parity.acquire.cta.shared::cta.b64 P, [%0], %1, 0x989680;\n\t"
        "@P bra D%=;\n\t"
        "bra W%=;\n\t"
        "D%=:\n\t"
        "}"
        :: "r"(addr), "r"(parity) : "memory");
}

// Exact first-index argmax merge: take (nv,ni) if strictly greater, or equal
// with smaller index.
__device__ __forceinline__ void amerge(float& b, int& bi, float nv, int ni) {
    if (nv > b || (nv == b && ni < bi)) { b = nv; bi = ni; }
}

__global__ __launch_bounds__(BLOCK_THREADS, 2)
void yolo_post_kernel(const float* __restrict__ in, float4* __restrict__ out4)
{
    extern __shared__ char sb[];
    const unsigned base = smem_u32(sb);
    float* const in_base  = reinterpret_cast<float*>(sb + SM_IN);
    float* const out_base = reinterpret_cast<float*>(sb + SM_OUT);

    const int tid  = threadIdx.x;
    const int b    = blockIdx.x;
    const int r    = tid >> 1;        // row within tile (0..127)
    const int half = tid & 1;         // 0: classes 0-39, 1: classes 40-79 (rot 8)

    // Contiguous chunk (quad-row granularity).
    const int q_start = QUADS_BASE * b + (b < QUADS_EXTRA ? b : QUADS_EXTRA);
    const int row0    = 4 * q_start;
    const int n_rows  = 4 * (QUADS_BASE + (b < QUADS_EXTRA ? 1 : 0));   // 1364 or 1360
    const int n_tiles = (n_rows + TILE_ROWS - 1) / TILE_ROWS;           // 11

    if (tid == 0) {
        mbar_init(base + 0, 1);
        mbar_init(base + 8, 1);
        int tr0 = (n_rows < TILE_ROWS) ? n_rows : TILE_ROWS;
        bulk_load(base + SM_IN, in + (size_t)row0 * N_CH,
                  (unsigned)(tr0 * N_CH * 4), base + 0);
    }
    __syncthreads();

    for (int it = 0; it < n_tiles; ++it) {
        const int slot   = it & 1;
        const int slot_w = (it + 1) & 1;

        // Issue DMA for next tile into the buffer freed last iteration.
        if (tid == 0 && it + 1 < n_tiles) {
            const int r_off = (it + 1) * TILE_ROWS;
            int tr = n_rows - r_off;
            if (tr > TILE_ROWS) tr = TILE_ROWS;
            bulk_load(base + SM_IN + slot_w * TILE_BYTES,
                      in + (size_t)(row0 + r_off) * N_CH,
                      (unsigned)(tr * N_CH * 4), base + slot_w * 8);
        }

        mbar_wait(base + slot * 8, (unsigned)((it >> 1) & 1));

        const int r_off = it * TILE_ROWS;
        int tile_rows = n_rows - r_off;
        if (tile_rows > TILE_ROWS) tile_rows = TILE_ROWS;

        // ---- compute: 2 threads per row, run unguarded (stale smem reads on
        //      short last tiles are discarded by the bounded store) ----
        const float* row = in_base + slot * TILE_FLOATS + r * N_CH;

        // Box/conf: both halves read the same words (broadcast, conflict-free).
        const float x    = row[0];
        const float y    = row[1];
        const float w    = row[2];
        const float h    = row[3];
        const float conf = row[4];

        // Class element layout per half (class index, element = 5 + class):
        //   half 0: class = j*10 + k                       (monotone)
        //   half 1: class = 40 + (j*10 + k + 8) % 40       (wraps only in j=3,k>=2)
        // Addresses: elem = 5 + class48 where
        //   j<3 :            class + 48*half                -> monotone per acc
        //   j=3, k<2:        30+k + 48*half                 (78,79 for half 1)
        //   j=3, k>=2:       30+k +  8*half                 (42..47 for half 1)
        const int h48 = 48 * half;
        const int h8  = 8 * half;

        float b0, b1, b2, b3;
        int   i0, i1, i2, i3;
        // init k=0
        i0 =  0 + h48; b0 = row[5 + i0];
        i1 = 10 + h48; b1 = row[5 + i1];
        i2 = 20 + h48; b2 = row[5 + i2];
        i3 = 30 + h48; b3 = row[5 + i3];   // j=3,k=0: 30+48*half (30 or 78)

        #pragma unroll
        for (int k = 1; k < 10; k++) {
            const int c0 =  0 + k + h48;
            const int c1 = 10 + k + h48;
            const int c2 = 20 + k + h48;
            const int c3 = (k < 2) ? (30 + k + h48) : (30 + k + h8);
            float v0 = row[5 + c0];
            float v1 = row[5 + c1];
            float v2 = row[5 + c2];
            float v3 = row[5 + c3];
            // acc0-2 monotone within: strict > keeps first index exactly.
            if (v0 > b0) { b0 = v0; i0 = c0; }
            if (v1 > b1) { b1 = v1; i1 = c1; }
            if (v2 > b2) { b2 = v2; i2 = c2; }
            // acc3 non-monotone for half 1 (78,79,42..47): exact tie-aware.
            amerge(b3, i3, v3, c3);
        }
        // Cross-acc merge: exact tie-aware (half 1's acc3 may hold lower
        // indices than acc0-2).
        amerge(b0, i0, b1, i1);
        amerge(b0, i0, b2, i2);
        amerge(b0, i0, b3, i3);

        // Pair combine across halves via shfl_xor(1); all 32 lanes active.
        {
            float tb = __shfl_xor_sync(0xFFFFFFFFu, b0, 1);
            int   ti = __shfl_xor_sync(0xFFFFFFFFu, i0, 1);
            amerge(b0, i0, tb, ti);
        }

        const float score = conf * b0;
        const bool  pass  = score > CONF_TH;
        const float hw = 0.5f * w;
        const float hh = 0.5f * h;

        float o0 = 0.f, o1 = 0.f, o2 = 0.f, o3 = 0.f, o4 = 0.f, o5 = 0.f;
        if (pass) {
            o0 = x - hw;
            o1 = y - hh;
            o2 = x + hw;
            o3 = y + hh;
            o4 = score;
            o5 = (float)i0;
        }

        // Stage: even lane writes floats 0-2, odd lane 3-5 (conflict-free).
        float* ob = out_base + (it & 1) * OUT_FLOATS;
        float* so = ob + r * N_OUT + 3 * half;
        if (half == 0) { so[0] = o0; so[1] = o1; so[2] = o2; }
        else           { so[0] = o3; so[1] = o4; so[2] = o5; }

        __syncthreads();   // LDS reads of in-buf done (slot reuse safe) + staging visible

        // ---- coalesced float4 store (tile_rows % 4 == 0) ----
        {
            const int nvec = (tile_rows * N_OUT) / 4;   // <= 192
            const float4* src = reinterpret_cast<const float4*>(ob);
            float4* dst = reinterpret_cast<float4*>(
                reinterpret_cast<float*>(out4) + (size_t)(row0 + r_off) * N_OUT);
            if (tid < nvec) dst[tid] = src[tid];
        }
    }
}

extern "C" void kernel_launch(void* const* d_in, const int* in_sizes, int n_in,
                              void* d_out, int out_size)
{
    const float* in  = (const float*)d_in[0];
    float4*      out = (float4*)d_out;
    cudaFuncSetAttribute(yolo_post_kernel,
                         cudaFuncAttributeMaxDynamicSharedMemorySize, SM_TOTAL);
    yolo_post_kernel<<<GRID_BLOCKS, BLOCK_THREADS, SM_TOTAL>>>(in, out);
}